// round 9
// baseline (speedup 1.0000x reference)
#include <cuda_runtime.h>
#include <cuda_bf16.h>
#include <cstdint>

// ---------------------------------------------------------------------------
// MultiHeadSelfAttention: B=128,H=128,F=8,D=200, nh=10, hd=20
// x flat: (131072, 200). Q/K/V/out projections: mma.sync bf16 3-pass split,
// double-buffered smem + cp.async. attn: 256-thr blocks of 64 queries x 4
// key-parts (fp32, split-K softmax w/o max-subtraction).
// ---------------------------------------------------------------------------

typedef unsigned long long u64;

// ---------------- fp32 scratch ----------------
__device__ float g_q[131072L * 200];
__device__ float g_k[131072L * 200];
__device__ float g_v[131072L * 200];
__device__ float g_ctx[131072L * 200];
// ---------------- bf16 split weights (transposed) ----------------
__device__ __nv_bfloat16 g_whi[3][208 * 256];
__device__ __nv_bfloat16 g_wlo[3][208 * 256];

// =========================== helpers =======================================
__device__ __forceinline__ uint32_t pkbf(float lo, float hi) {
    uint32_t r;
    asm("cvt.rn.bf16x2.f32 %0, %1, %2;" : "=r"(r) : "f"(hi), "f"(lo));
    return r;
}
__device__ __forceinline__ float bf_lo(uint32_t p) { return __uint_as_float(p << 16); }
__device__ __forceinline__ float bf_hi(uint32_t p) { return __uint_as_float(p & 0xFFFF0000u); }

__device__ __forceinline__ void mma_bf16(float* d, const uint32_t* a,
                                         uint32_t b0, uint32_t b1) {
    asm volatile(
        "mma.sync.aligned.m16n8k16.row.col.f32.bf16.bf16.f32 "
        "{%0,%1,%2,%3}, {%4,%5,%6,%7}, {%8,%9}, {%0,%1,%2,%3};"
        : "+f"(d[0]), "+f"(d[1]), "+f"(d[2]), "+f"(d[3])
        : "r"(a[0]), "r"(a[1]), "r"(a[2]), "r"(a[3]), "r"(b0), "r"(b1));
}
__device__ __forceinline__ uint32_t smem_u32(const void* p) {
    uint32_t a;
    asm("{ .reg .u64 t; cvta.to.shared.u64 t, %1; cvt.u32.u64 %0, t; }"
        : "=r"(a) : "l"(p));
    return a;
}
__device__ __forceinline__ void cp16(uint32_t dst, const void* src) {
    asm volatile("cp.async.ca.shared.global [%0], [%1], 16;"
                 :: "r"(dst), "l"(src) : "memory");
}
#define CP_COMMIT() asm volatile("cp.async.commit_group;" ::: "memory")
#define CP_WAIT0()  asm volatile("cp.async.wait_group 0;" ::: "memory")

// =================== W -> Wt[208][256] bf16 hi/lo (transpose+split) ========
__global__ __launch_bounds__(256)
void conv_wt(const float* __restrict__ W, __nv_bfloat16* __restrict__ hi,
             __nv_bfloat16* __restrict__ lo) {
    int idx = blockIdx.x * 256 + threadIdx.x;     // over 208*256
    int n = idx >> 8, k = idx & 255;
    float v = (n < 200 && k < 200) ? W[k * 200 + n] : 0.f;
    __nv_bfloat16 h = __float2bfloat16(v);
    float r = v - __bfloat162float(h);
    hi[idx] = h;
    lo[idx] = __float2bfloat16(r);
}

// ============== mma.sync bf16-split GEMM, double-buffered ==================
// C[131072x200] = A(fp32) @ Wt^T. Block 128 x 208, 8 warps = 4(M) x 2(N).
// Stage layout (pitch 144B rows): AH 0, AL 18432, BH 36864, BL 66816.
#define AH_OFF 0
#define AL_OFF 18432
#define BH_OFF 36864
#define BL_OFF 66816
#define STG    96768
#define GEMM_SMEM (2 * STG)   // 193536 B

__device__ __forceinline__ void load_a_chunk(const float* __restrict__ A,
                                             long row0, int tid, int kb,
                                             float4* abuf) {
    int r = tid >> 1, half = tid & 1;
    const float* ap = A + (row0 + r) * 200;
    #pragma unroll
    for (int q = 0; q < 8; q++) {
        int col0 = kb + half * 32 + q * 4;
        abuf[q] = (col0 < 200) ? *(const float4*)(ap + col0)
                               : make_float4(0.f, 0.f, 0.f, 0.f);
    }
}

__device__ __forceinline__ void conv_a_to_smem(char* stage, int tid,
                                               const float4* abuf) {
    int r = tid >> 1, half = tid & 1;
    char* ahp = stage + AH_OFF + r * 144 + half * 64;
    char* alp = stage + AL_OFF + r * 144 + half * 64;
    #pragma unroll
    for (int q = 0; q < 8; q++) {
        float4 v = abuf[q];
        uint32_t h01 = pkbf(v.x, v.y);
        uint32_t h23 = pkbf(v.z, v.w);
        float rx = v.x - bf_lo(h01), ry = v.y - bf_hi(h01);
        float rz = v.z - bf_lo(h23), rw = v.w - bf_hi(h23);
        uint32_t l01 = pkbf(rx, ry);
        uint32_t l23 = pkbf(rz, rw);
        *(uint32_t*)(ahp + q * 8)     = h01;
        *(uint32_t*)(ahp + q * 8 + 4) = h23;
        *(uint32_t*)(alp + q * 8)     = l01;
        *(uint32_t*)(alp + q * 8 + 4) = l23;
    }
}

__device__ __forceinline__ void issue_b_cpasync(uint32_t sbase, int tid,
                                                const __nv_bfloat16* Bh,
                                                const __nv_bfloat16* Bl, int kb) {
    // 208 rows x 8 x 16B per buffer = 1664 units
    #pragma unroll
    for (int i = 0; i < 7; i++) {
        int e = tid + i * 256;
        if (e < 1664) {
            int n = e >> 3, u = e & 7;
            cp16(sbase + BH_OFF + n * 144 + u * 16, Bh + n * 256 + kb + u * 8);
            cp16(sbase + BL_OFF + n * 144 + u * 16, Bl + n * 256 + kb + u * 8);
        }
    }
    CP_COMMIT();
}

__global__ __launch_bounds__(256, 1)
void gemm_mma(const float* __restrict__ A,
              const __nv_bfloat16* __restrict__ Bh,
              const __nv_bfloat16* __restrict__ Bl,
              float* __restrict__ C) {
    extern __shared__ char smem[];
    const int tid  = threadIdx.x;
    const int wid  = tid >> 5, lane = tid & 31;
    const int wm   = wid >> 1, wn = wid & 1;
    const int g    = lane >> 2, t = lane & 3;
    const long row0 = (long)blockIdx.x * 128;

    float acc[2][13][4];
    #pragma unroll
    for (int mt = 0; mt < 2; mt++)
        #pragma unroll
        for (int nt = 0; nt < 13; nt++)
            #pragma unroll
            for (int e = 0; e < 4; e++) acc[mt][nt][e] = 0.f;

    float4 abuf[8];

    // -------- prologue: fill stage 0, prefetch A chunk 1 --------
    load_a_chunk(A, row0, tid, 0, abuf);
    issue_b_cpasync(smem_u32(smem), tid, Bh, Bl, 0);
    conv_a_to_smem(smem, tid, abuf);
    load_a_chunk(A, row0, tid, 64, abuf);
    CP_WAIT0();
    __syncthreads();

    #pragma unroll 1
    for (int c = 0; c < 4; c++) {
        char* stage  = smem + (c & 1) * STG;
        char* stageN = smem + ((c + 1) & 1) * STG;

        if (c < 3)
            issue_b_cpasync(smem_u32(stageN), tid, Bh, Bl, (c + 1) * 64);

        const uint32_t* AH32 = (const uint32_t*)(stage + AH_OFF);
        const uint32_t* AL32 = (const uint32_t*)(stage + AL_OFF);
        const uint32_t* BH32 = (const uint32_t*)(stage + BH_OFF);
        const uint32_t* BL32 = (const uint32_t*)(stage + BL_OFF);

        const int nst = (c < 3) ? 4 : 1;     // K=208 total
        #pragma unroll 1
        for (int ks = 0; ks < nst; ks++) {
            uint32_t ah[2][4], al[2][4];
            #pragma unroll
            for (int mt = 0; mt < 2; mt++) {
                int r0 = wm * 32 + mt * 16 + g;
                int base = r0 * 36 + ks * 8 + t;
                ah[mt][0] = AH32[base];
                ah[mt][1] = AH32[base + 8 * 36];
                ah[mt][2] = AH32[base + 4];
                ah[mt][3] = AH32[base + 8 * 36 + 4];
                al[mt][0] = AL32[base];
                al[mt][1] = AL32[base + 8 * 36];
                al[mt][2] = AL32[base + 4];
                al[mt][3] = AL32[base + 8 * 36 + 4];
            }
            #pragma unroll
            for (int nt = 0; nt < 13; nt++) {
                int n = wn * 104 + nt * 8 + g;
                int bb = n * 36 + ks * 8 + t;
                uint32_t bh0 = BH32[bb], bh1 = BH32[bb + 4];
                uint32_t bl0 = BL32[bb], bl1 = BL32[bb + 4];
                #pragma unroll
                for (int mt = 0; mt < 2; mt++) {
                    mma_bf16(acc[mt][nt], ah[mt], bh0, bh1);
                    mma_bf16(acc[mt][nt], ah[mt], bl0, bl1);
                    mma_bf16(acc[mt][nt], al[mt], bh0, bh1);
                }
            }
        }

        if (c < 3) {
            conv_a_to_smem(stageN, tid, abuf);           // chunk c+1 -> stage^1
            if (c < 2) load_a_chunk(A, row0, tid, (c + 2) * 64, abuf);
            CP_WAIT0();
        }
        __syncthreads();
    }

    #pragma unroll
    for (int mt = 0; mt < 2; mt++) {
        long r0 = row0 + wm * 32 + mt * 16 + g;
        #pragma unroll
        for (int nt = 0; nt < 13; nt++) {
            int col = wn * 104 + nt * 8 + t * 2;
            if (col < 200) {
                *(float2*)(C + r0 * 200 + col) =
                    make_float2(acc[mt][nt][0], acc[mt][nt][1]);
                *(float2*)(C + (r0 + 8) * 200 + col) =
                    make_float2(acc[mt][nt][2], acc[mt][nt][3]);
            }
        }
    }
}

// ============ Attention: 64 queries x 4 key-parts per block =================
// Block (i, h, qb): queries [qb*64, qb*64+64). thread = (q = tid&63, part).
// Each thread: 32 keys. Scores bounded -> exp without max-subtraction.
// smem 70656 B -> 3 blocks/SM (24 warps).
__global__ __launch_bounds__(256, 3)
void attn64(const float* __restrict__ Q, const float* __restrict__ K,
            const float* __restrict__ V, float* __restrict__ AW,
            float* __restrict__ CTX) {
    extern __shared__ float sm[];
    float* ks   = sm;                        // 128*20 (scale folded in)
    float* vs   = sm + 2560;                 // 128*20
    float* es   = sm + 5120;                 // 64*132
    float* sinv = sm + 5120 + 64 * 132;      // 64
    float* sp   = sinv + 64;                 // 3*64 partial sums
    float* op   = sp + 192;                  // 3*64*20 partial AV

    const int i    = blockIdx.x;
    const int h    = blockIdx.y;
    const int qb   = blockIdx.z;
    const int tid  = threadIdx.x;
    const int q    = tid & 63;
    const int part = tid >> 6;
    const long rb  = (long)i * 128;
    const int hoff = h * 20;
    const float scale = 0.22360679774997896f;   // 1/sqrt(20)

    // K (pre-scaled) and V head slices: 640 float4 each, 256 threads.
    {
        float4* ks4 = (float4*)ks;
        float4* vs4 = (float4*)vs;
        #pragma unroll
        for (int e0 = 0; e0 < 3; e0++) {
            int e = tid + e0 * 256;
            if (e < 640) {
                int r = e / 5, c = e - r * 5;
                float4 k4 = *(const float4*)(K + (rb + r) * 200 + hoff + c * 4);
                k4.x *= scale; k4.y *= scale; k4.z *= scale; k4.w *= scale;
                ks4[e] = k4;
                vs4[e] = *(const float4*)(V + (rb + r) * 200 + hoff + c * 4);
            }
        }
    }
    // q row -> registers (4 parts load the same row; L1 broadcast).
    const long qg = rb + qb * 64 + q;
    float qr[20];
    {
        const float* qp = Q + qg * 200 + hoff;
        #pragma unroll
        for (int c = 0; c < 5; c++) {
            float4 t4 = *(const float4*)(qp + c * 4);
            qr[c * 4 + 0] = t4.x; qr[c * 4 + 1] = t4.y;
            qr[c * 4 + 2] = t4.z; qr[c * 4 + 3] = t4.w;
        }
    }
    __syncthreads();

    const int t0 = part * 32;
    float o[20];
    #pragma unroll
    for (int j = 0; j < 20; j++) o[j] = 0.f;
    float ssum = 0.f;
    float eb0, eb1, eb2;
    float* myrow = es + q * 132;

    #pragma unroll 2
    for (int tt = 0; tt < 32; tt++) {
        const int t = t0 + tt;
        const float4* kt = (const float4*)(ks + t * 20);   // warp broadcast
        float acc = 0.f;
        #pragma unroll
        for (int c = 0; c < 5; c++) {
            float4 k4 = kt[c];
            acc += qr[c * 4 + 0] * k4.x + qr[c * 4 + 1] * k4.y
                 + qr[c * 4 + 2] * k4.z + qr[c * 4 + 3] * k4.w;
        }
        float e = __expf(acc);
        ssum += e;
        int ph = tt & 3;
        if (ph == 0)      eb0 = e;
        else if (ph == 1) eb1 = e;
        else if (ph == 2) eb2 = e;
        else *(float4*)(myrow + (t - 3)) = make_float4(eb0, eb1, eb2, e);
        const float4* vt = (const float4*)(vs + t * 20);   // warp broadcast
        #pragma unroll
        for (int c = 0; c < 5; c++) {
            float4 v4 = vt[c];
            o[c * 4 + 0] += e * v4.x; o[c * 4 + 1] += e * v4.y;
            o[c * 4 + 2] += e * v4.z; o[c * 4 + 3] += e * v4.w;
        }
    }

    // combine parts
    if (part > 0) {
        sp[(part - 1) * 64 + q] = ssum;
        float* od = op + ((part - 1) * 64 + q) * 20;
        #pragma unroll
        for (int c = 0; c < 5; c++)
            *(float4*)(od + c * 4) = make_float4(o[c * 4 + 0], o[c * 4 + 1],
                                                 o[c * 4 + 2], o[c * 4 + 3]);
    }
    __syncthreads();
    if (part == 0) {
        const float inv = 1.0f / (ssum + sp[q] + sp[64 + q] + sp[128 + q]);
        sinv[q] = inv;
        float* cp = CTX + qg * 200 + hoff;
        #pragma unroll
        for (int c = 0; c < 5; c++) {
            float4 p1 = *(const float4*)(op + (q * 20)        + c * 4);
            float4 p2 = *(const float4*)(op + ((64 + q) * 20) + c * 4);
            float4 p3 = *(const float4*)(op + ((128 + q) * 20) + c * 4);
            *(float4*)(cp + c * 4) = make_float4(
                (o[c * 4 + 0] + p1.x + p2.x + p3.x) * inv,
                (o[c * 4 + 1] + p1.y + p2.y + p3.y) * inv,
                (o[c * 4 + 2] + p1.z + p2.z + p3.z) * inv,
                (o[c * 4 + 3] + p1.w + p2.w + p3.w) * inv);
        }
    }
    __syncthreads();

    // Coalesced attention-weight store: 2048 float4, 256 threads x 8.
    {
        float4* awp = (float4*)(AW + (long)(i * 10 + h) * 16384
                                   + (long)qb * 64 * 128);
        #pragma unroll
        for (int e0 = 0; e0 < 8; e0++) {
            int e = tid + e0 * 256;
            int s = e >> 5;
            int l = e & 31;
            float4 v4 = *(const float4*)(es + s * 132 + l * 4);
            float iv = sinv[s];
            awp[e] = make_float4(v4.x * iv, v4.y * iv, v4.z * iv, v4.w * iv);
        }
    }
}

// ---------------------------------------------------------------------------
extern "C" void kernel_launch(void* const* d_in, const int* in_sizes, int n_in,
                              void* d_out, int out_size) {
    const float* x  = (const float*)d_in[0];
    const float* wq = (const float*)d_in[1];
    const float* wk = (const float*)d_in[2];
    const float* wv = (const float*)d_in[3];

    float* attn = (float*)d_out;                       // 1024*10*128*128
    float* out  = (float*)d_out + 167772160L;          // 131072*200

    float *gq, *gk, *gv, *gctx;
    __nv_bfloat16 *whi, *wlo;
    cudaGetSymbolAddress((void**)&gq,   g_q);
    cudaGetSymbolAddress((void**)&gk,   g_k);
    cudaGetSymbolAddress((void**)&gv,   g_v);
    cudaGetSymbolAddress((void**)&gctx, g_ctx);
    cudaGetSymbolAddress((void**)&whi,  g_whi);
    cudaGetSymbolAddress((void**)&wlo,  g_wlo);

    // 2560+2560+8448+64+192+3840 = 17664 floats = 70656 B
    const int AT_SMEM = 17664 * 4;
    cudaFuncSetAttribute(gemm_mma, cudaFuncAttributeMaxDynamicSharedMemorySize, GEMM_SMEM);
    cudaFuncSetAttribute(attn64,   cudaFuncAttributeMaxDynamicSharedMemorySize, AT_SMEM);

    const int WSZ = 208 * 256;

    conv_wt<<<208, 256>>>(wq, whi + 0 * WSZ, wlo + 0 * WSZ);
    conv_wt<<<208, 256>>>(wk, whi + 1 * WSZ, wlo + 1 * WSZ);
    conv_wt<<<208, 256>>>(wv, whi + 2 * WSZ, wlo + 2 * WSZ);

    gemm_mma<<<1024, 256, GEMM_SMEM>>>(x, whi + 0 * WSZ, wlo + 0 * WSZ, gq);
    gemm_mma<<<1024, 256, GEMM_SMEM>>>(x, whi + 1 * WSZ, wlo + 1 * WSZ, gk);
    gemm_mma<<<1024, 256, GEMM_SMEM>>>(x, whi + 2 * WSZ, wlo + 2 * WSZ, gv);

    attn64<<<dim3(1024, 10, 2), 256, AT_SMEM>>>(gq, gk, gv, attn, gctx);

    gemm_mma<<<1024, 256, GEMM_SMEM>>>(gctx, whi + 0 * WSZ, wlo + 0 * WSZ, out);
}

// round 10
// speedup vs baseline: 1.1160x; 1.1160x over previous
#include <cuda_runtime.h>
#include <cuda_bf16.h>
#include <cstdint>

// ---------------------------------------------------------------------------
// MultiHeadSelfAttention: B=128,H=128,F=8,D=200, nh=10, hd=20
// x flat: (131072, 200). Q/K/V/out projections: mma.sync bf16 3-pass split,
// double-buffered smem + cp.async (R9). attn: 256-thr split-K (R8 shape) with
// ILP-split dot chains.
// ---------------------------------------------------------------------------

typedef unsigned long long u64;

// ---------------- fp32 scratch ----------------
__device__ float g_q[131072L * 200];
__device__ float g_k[131072L * 200];
__device__ float g_v[131072L * 200];
__device__ float g_ctx[131072L * 200];
// ---------------- bf16 split weights (transposed) ----------------
__device__ __nv_bfloat16 g_whi[3][208 * 256];
__device__ __nv_bfloat16 g_wlo[3][208 * 256];

// =========================== helpers =======================================
__device__ __forceinline__ uint32_t pkbf(float lo, float hi) {
    uint32_t r;
    asm("cvt.rn.bf16x2.f32 %0, %1, %2;" : "=r"(r) : "f"(hi), "f"(lo));
    return r;
}
__device__ __forceinline__ float bf_lo(uint32_t p) { return __uint_as_float(p << 16); }
__device__ __forceinline__ float bf_hi(uint32_t p) { return __uint_as_float(p & 0xFFFF0000u); }

__device__ __forceinline__ void mma_bf16(float* d, const uint32_t* a,
                                         uint32_t b0, uint32_t b1) {
    asm volatile(
        "mma.sync.aligned.m16n8k16.row.col.f32.bf16.bf16.f32 "
        "{%0,%1,%2,%3}, {%4,%5,%6,%7}, {%8,%9}, {%0,%1,%2,%3};"
        : "+f"(d[0]), "+f"(d[1]), "+f"(d[2]), "+f"(d[3])
        : "r"(a[0]), "r"(a[1]), "r"(a[2]), "r"(a[3]), "r"(b0), "r"(b1));
}
__device__ __forceinline__ uint32_t smem_u32(const void* p) {
    uint32_t a;
    asm("{ .reg .u64 t; cvta.to.shared.u64 t, %1; cvt.u32.u64 %0, t; }"
        : "=r"(a) : "l"(p));
    return a;
}
__device__ __forceinline__ void cp16(uint32_t dst, const void* src) {
    asm volatile("cp.async.ca.shared.global [%0], [%1], 16;"
                 :: "r"(dst), "l"(src) : "memory");
}
#define CP_COMMIT() asm volatile("cp.async.commit_group;" ::: "memory")
#define CP_WAIT0()  asm volatile("cp.async.wait_group 0;" ::: "memory")

// =================== W -> Wt[208][256] bf16 hi/lo (transpose+split) ========
__global__ __launch_bounds__(256)
void conv_wt(const float* __restrict__ W, __nv_bfloat16* __restrict__ hi,
             __nv_bfloat16* __restrict__ lo) {
    int idx = blockIdx.x * 256 + threadIdx.x;     // over 208*256
    int n = idx >> 8, k = idx & 255;
    float v = (n < 200 && k < 200) ? W[k * 200 + n] : 0.f;
    __nv_bfloat16 h = __float2bfloat16(v);
    float r = v - __bfloat162float(h);
    hi[idx] = h;
    lo[idx] = __float2bfloat16(r);
}

// ============== mma.sync bf16-split GEMM, double-buffered (R9) =============
#define AH_OFF 0
#define AL_OFF 18432
#define BH_OFF 36864
#define BL_OFF 66816
#define STG    96768
#define GEMM_SMEM (2 * STG)   // 193536 B

__device__ __forceinline__ void load_a_chunk(const float* __restrict__ A,
                                             long row0, int tid, int kb,
                                             float4* abuf) {
    int r = tid >> 1, half = tid & 1;
    const float* ap = A + (row0 + r) * 200;
    #pragma unroll
    for (int q = 0; q < 8; q++) {
        int col0 = kb + half * 32 + q * 4;
        abuf[q] = (col0 < 200) ? *(const float4*)(ap + col0)
                               : make_float4(0.f, 0.f, 0.f, 0.f);
    }
}

__device__ __forceinline__ void conv_a_to_smem(char* stage, int tid,
                                               const float4* abuf) {
    int r = tid >> 1, half = tid & 1;
    char* ahp = stage + AH_OFF + r * 144 + half * 64;
    char* alp = stage + AL_OFF + r * 144 + half * 64;
    #pragma unroll
    for (int q = 0; q < 8; q++) {
        float4 v = abuf[q];
        uint32_t h01 = pkbf(v.x, v.y);
        uint32_t h23 = pkbf(v.z, v.w);
        float rx = v.x - bf_lo(h01), ry = v.y - bf_hi(h01);
        float rz = v.z - bf_lo(h23), rw = v.w - bf_hi(h23);
        uint32_t l01 = pkbf(rx, ry);
        uint32_t l23 = pkbf(rz, rw);
        *(uint32_t*)(ahp + q * 8)     = h01;
        *(uint32_t*)(ahp + q * 8 + 4) = h23;
        *(uint32_t*)(alp + q * 8)     = l01;
        *(uint32_t*)(alp + q * 8 + 4) = l23;
    }
}

__device__ __forceinline__ void issue_b_cpasync(uint32_t sbase, int tid,
                                                const __nv_bfloat16* Bh,
                                                const __nv_bfloat16* Bl, int kb) {
    #pragma unroll
    for (int i = 0; i < 7; i++) {
        int e = tid + i * 256;
        if (e < 1664) {
            int n = e >> 3, u = e & 7;
            cp16(sbase + BH_OFF + n * 144 + u * 16, Bh + n * 256 + kb + u * 8);
            cp16(sbase + BL_OFF + n * 144 + u * 16, Bl + n * 256 + kb + u * 8);
        }
    }
    CP_COMMIT();
}

__global__ __launch_bounds__(256, 1)
void gemm_mma(const float* __restrict__ A,
              const __nv_bfloat16* __restrict__ Bh,
              const __nv_bfloat16* __restrict__ Bl,
              float* __restrict__ C) {
    extern __shared__ char smem[];
    const int tid  = threadIdx.x;
    const int wid  = tid >> 5, lane = tid & 31;
    const int wm   = wid >> 1, wn = wid & 1;
    const int g    = lane >> 2, t = lane & 3;
    const long row0 = (long)blockIdx.x * 128;

    float acc[2][13][4];
    #pragma unroll
    for (int mt = 0; mt < 2; mt++)
        #pragma unroll
        for (int nt = 0; nt < 13; nt++)
            #pragma unroll
            for (int e = 0; e < 4; e++) acc[mt][nt][e] = 0.f;

    float4 abuf[8];

    load_a_chunk(A, row0, tid, 0, abuf);
    issue_b_cpasync(smem_u32(smem), tid, Bh, Bl, 0);
    conv_a_to_smem(smem, tid, abuf);
    load_a_chunk(A, row0, tid, 64, abuf);
    CP_WAIT0();
    __syncthreads();

    #pragma unroll 1
    for (int c = 0; c < 4; c++) {
        char* stage  = smem + (c & 1) * STG;
        char* stageN = smem + ((c + 1) & 1) * STG;

        if (c < 3)
            issue_b_cpasync(smem_u32(stageN), tid, Bh, Bl, (c + 1) * 64);

        const uint32_t* AH32 = (const uint32_t*)(stage + AH_OFF);
        const uint32_t* AL32 = (const uint32_t*)(stage + AL_OFF);
        const uint32_t* BH32 = (const uint32_t*)(stage + BH_OFF);
        const uint32_t* BL32 = (const uint32_t*)(stage + BL_OFF);

        const int nst = (c < 3) ? 4 : 1;
        #pragma unroll 1
        for (int ks = 0; ks < nst; ks++) {
            uint32_t ah[2][4], al[2][4];
            #pragma unroll
            for (int mt = 0; mt < 2; mt++) {
                int r0 = wm * 32 + mt * 16 + g;
                int base = r0 * 36 + ks * 8 + t;
                ah[mt][0] = AH32[base];
                ah[mt][1] = AH32[base + 8 * 36];
                ah[mt][2] = AH32[base + 4];
                ah[mt][3] = AH32[base + 8 * 36 + 4];
                al[mt][0] = AL32[base];
                al[mt][1] = AL32[base + 8 * 36];
                al[mt][2] = AL32[base + 4];
                al[mt][3] = AL32[base + 8 * 36 + 4];
            }
            #pragma unroll
            for (int nt = 0; nt < 13; nt++) {
                int n = wn * 104 + nt * 8 + g;
                int bb = n * 36 + ks * 8 + t;
                uint32_t bh0 = BH32[bb], bh1 = BH32[bb + 4];
                uint32_t bl0 = BL32[bb], bl1 = BL32[bb + 4];
                #pragma unroll
                for (int mt = 0; mt < 2; mt++) {
                    mma_bf16(acc[mt][nt], ah[mt], bh0, bh1);
                    mma_bf16(acc[mt][nt], ah[mt], bl0, bl1);
                    mma_bf16(acc[mt][nt], al[mt], bh0, bh1);
                }
            }
        }

        if (c < 3) {
            conv_a_to_smem(stageN, tid, abuf);
            if (c < 2) load_a_chunk(A, row0, tid, (c + 2) * 64, abuf);
            CP_WAIT0();
        }
        __syncthreads();
    }

    #pragma unroll
    for (int mt = 0; mt < 2; mt++) {
        long r0 = row0 + wm * 32 + mt * 16 + g;
        #pragma unroll
        for (int nt = 0; nt < 13; nt++) {
            int col = wn * 104 + nt * 8 + t * 2;
            if (col < 200) {
                *(float2*)(C + r0 * 200 + col) =
                    make_float2(acc[mt][nt][0], acc[mt][nt][1]);
                *(float2*)(C + (r0 + 8) * 200 + col) =
                    make_float2(acc[mt][nt][2], acc[mt][nt][3]);
            }
        }
    }
}

// ================= Attention per (i, h): 256-thread split-K =================
// thread = (q = tid&127, half = tid>>7); each handles 64 keys.
// ILP: 4-way split dot accumulators + dual running sums.
__global__ __launch_bounds__(256, 2)
void attn256(const float* __restrict__ Q, const float* __restrict__ K,
             const float* __restrict__ V, float* __restrict__ AW,
             float* __restrict__ CTX) {
    extern __shared__ float sm[];
    float* ks   = sm;                        // 128*20 (scale folded in)
    float* vs   = sm + 2560;                 // 128*20
    float* es   = sm + 5120;                 // 128*132
    float* sinv = sm + 5120 + 128 * 132;     // 128
    float* sp   = sinv + 128;                // 128 partial sums (half=1)
    float* op   = sp + 128;                  // 128*20 partial AV (half=1)

    const int i    = blockIdx.x;
    const int h    = blockIdx.y;
    const int tid  = threadIdx.x;
    const int q    = tid & 127;
    const int half = tid >> 7;
    const long rb  = (long)i * 128;
    const int hoff = h * 20;
    const float scale = 0.22360679774997896f;   // 1/sqrt(20)

    {
        float4* ks4 = (float4*)ks;
        float4* vs4 = (float4*)vs;
        #pragma unroll
        for (int e0 = 0; e0 < 3; e0++) {
            int e = tid + e0 * 256;
            if (e < 640) {
                int r = e / 5, c = e - r * 5;
                float4 k4 = *(const float4*)(K + (rb + r) * 200 + hoff + c * 4);
                k4.x *= scale; k4.y *= scale; k4.z *= scale; k4.w *= scale;
                ks4[e] = k4;
                vs4[e] = *(const float4*)(V + (rb + r) * 200 + hoff + c * 4);
            }
        }
    }
    float qr[20];
    {
        const float* qp = Q + (rb + q) * 200 + hoff;
        #pragma unroll
        for (int c = 0; c < 5; c++) {
            float4 t4 = *(const float4*)(qp + c * 4);
            qr[c * 4 + 0] = t4.x; qr[c * 4 + 1] = t4.y;
            qr[c * 4 + 2] = t4.z; qr[c * 4 + 3] = t4.w;
        }
    }
    __syncthreads();

    const int t0 = half * 64;
    float o[20];
    #pragma unroll
    for (int j = 0; j < 20; j++) o[j] = 0.f;
    float ssum0 = 0.f, ssum1 = 0.f;
    float eb0, eb1, eb2;
    float* myrow = es + q * 132;

    #pragma unroll 2
    for (int tt = 0; tt < 64; tt++) {
        const int t = t0 + tt;
        const float4* kt = (const float4*)(ks + t * 20);   // warp broadcast
        // 4-way split dot: chain depth 5 FMA instead of 20
        float4 k0 = kt[0], k1 = kt[1], k2 = kt[2], k3 = kt[3], k4 = kt[4];
        float a0 = qr[0] * k0.x + qr[4] * k1.x;
        float a1 = qr[1] * k0.y + qr[5] * k1.y;
        float a2 = qr[2] * k0.z + qr[6] * k1.z;
        float a3 = qr[3] * k0.w + qr[7] * k1.w;
        a0 += qr[8]  * k2.x + qr[12] * k3.x;
        a1 += qr[9]  * k2.y + qr[13] * k3.y;
        a2 += qr[10] * k2.z + qr[14] * k3.z;
        a3 += qr[11] * k2.w + qr[15] * k3.w;
        a0 += qr[16] * k4.x;
        a1 += qr[17] * k4.y;
        a2 += qr[18] * k4.z;
        a3 += qr[19] * k4.w;
        float e = __expf((a0 + a1) + (a2 + a3));
        if (tt & 1) ssum1 += e; else ssum0 += e;
        int ph = tt & 3;
        if (ph == 0)      eb0 = e;
        else if (ph == 1) eb1 = e;
        else if (ph == 2) eb2 = e;
        else *(float4*)(myrow + (t - 3)) = make_float4(eb0, eb1, eb2, e);
        const float4* vt = (const float4*)(vs + t * 20);   // warp broadcast
        #pragma unroll
        for (int c = 0; c < 5; c++) {
            float4 v4 = vt[c];
            o[c * 4 + 0] += e * v4.x; o[c * 4 + 1] += e * v4.y;
            o[c * 4 + 2] += e * v4.z; o[c * 4 + 3] += e * v4.w;
        }
    }
    float ssum = ssum0 + ssum1;

    if (half == 1) {
        sp[q] = ssum;
        float* od = op + q * 20;
        #pragma unroll
        for (int c = 0; c < 5; c++)
            *(float4*)(od + c * 4) = make_float4(o[c * 4 + 0], o[c * 4 + 1],
                                                 o[c * 4 + 2], o[c * 4 + 3]);
    }
    __syncthreads();
    if (half == 0) {
        const float inv = 1.0f / (ssum + sp[q]);
        sinv[q] = inv;
        const float* od = op + q * 20;
        float* cp = CTX + (rb + q) * 200 + hoff;
        #pragma unroll
        for (int c = 0; c < 5; c++) {
            float4 p4 = *(const float4*)(od + c * 4);
            *(float4*)(cp + c * 4) = make_float4(
                (o[c * 4 + 0] + p4.x) * inv, (o[c * 4 + 1] + p4.y) * inv,
                (o[c * 4 + 2] + p4.z) * inv, (o[c * 4 + 3] + p4.w) * inv);
        }
    }
    __syncthreads();

    {
        float4* awp = (float4*)(AW + (long)(i * 10 + h) * 16384);
        #pragma unroll
        for (int e0 = 0; e0 < 16; e0++) {
            int e = tid + e0 * 256;
            int s = e >> 5;
            int l = e & 31;
            float4 v4 = *(const float4*)(es + s * 132 + l * 4);
            float iv = sinv[s];
            awp[e] = make_float4(v4.x * iv, v4.y * iv, v4.z * iv, v4.w * iv);
        }
    }
}

// ---------------------------------------------------------------------------
extern "C" void kernel_launch(void* const* d_in, const int* in_sizes, int n_in,
                              void* d_out, int out_size) {
    const float* x  = (const float*)d_in[0];
    const float* wq = (const float*)d_in[1];
    const float* wk = (const float*)d_in[2];
    const float* wv = (const float*)d_in[3];

    float* attn = (float*)d_out;                       // 1024*10*128*128
    float* out  = (float*)d_out + 167772160L;          // 131072*200

    float *gq, *gk, *gv, *gctx;
    __nv_bfloat16 *whi, *wlo;
    cudaGetSymbolAddress((void**)&gq,   g_q);
    cudaGetSymbolAddress((void**)&gk,   g_k);
    cudaGetSymbolAddress((void**)&gv,   g_v);
    cudaGetSymbolAddress((void**)&gctx, g_ctx);
    cudaGetSymbolAddress((void**)&whi,  g_whi);
    cudaGetSymbolAddress((void**)&wlo,  g_wlo);

    const int AT_SMEM = 24832 * 4;   // 99328 B
    cudaFuncSetAttribute(gemm_mma, cudaFuncAttributeMaxDynamicSharedMemorySize, GEMM_SMEM);
    cudaFuncSetAttribute(attn256,  cudaFuncAttributeMaxDynamicSharedMemorySize, AT_SMEM);

    const int WSZ = 208 * 256;

    conv_wt<<<208, 256>>>(wq, whi + 0 * WSZ, wlo + 0 * WSZ);
    conv_wt<<<208, 256>>>(wk, whi + 1 * WSZ, wlo + 1 * WSZ);
    conv_wt<<<208, 256>>>(wv, whi + 2 * WSZ, wlo + 2 * WSZ);

    gemm_mma<<<1024, 256, GEMM_SMEM>>>(x, whi + 0 * WSZ, wlo + 0 * WSZ, gq);
    gemm_mma<<<1024, 256, GEMM_SMEM>>>(x, whi + 1 * WSZ, wlo + 1 * WSZ, gk);
    gemm_mma<<<1024, 256, GEMM_SMEM>>>(x, whi + 2 * WSZ, wlo + 2 * WSZ, gv);

    attn256<<<dim3(1024, 10), 256, AT_SMEM>>>(gq, gk, gv, attn, gctx);

    gemm_mma<<<1024, 256, GEMM_SMEM>>>(gctx, whi + 0 * WSZ, wlo + 0 * WSZ, out);
}

// round 12
// speedup vs baseline: 1.1350x; 1.0170x over previous
#include <cuda_runtime.h>
#include <cuda_bf16.h>
#include <cstdint>

// ---------------------------------------------------------------------------
// MultiHeadSelfAttention: B=128,H=128,F=8,D=200, nh=10, hd=20
// x flat: (131072, 200). Q/K/V/out projections: mma.sync bf16 3-pass split,
// 64x224 blocks, 2 blocks/SM. attn: 256-thr split-K fp32 (R10).
// ---------------------------------------------------------------------------

typedef unsigned long long u64;

// ---------------- fp32 scratch ----------------
__device__ float g_q[131072L * 200];
__device__ float g_k[131072L * 200];
__device__ float g_v[131072L * 200];
__device__ float g_ctx[131072L * 200];
// ---------------- bf16 split weights (transposed, padded to 224x256) -------
__device__ __nv_bfloat16 g_whi[3][224 * 256];
__device__ __nv_bfloat16 g_wlo[3][224 * 256];

// =========================== helpers =======================================
__device__ __forceinline__ uint32_t pkbf(float lo, float hi) {
    uint32_t r;
    asm("cvt.rn.bf16x2.f32 %0, %1, %2;" : "=r"(r) : "f"(hi), "f"(lo));
    return r;
}
__device__ __forceinline__ float bf_lo(uint32_t p) { return __uint_as_float(p << 16); }
__device__ __forceinline__ float bf_hi(uint32_t p) { return __uint_as_float(p & 0xFFFF0000u); }

__device__ __forceinline__ void mma_bf16(float* d, const uint32_t* a,
                                         uint32_t b0, uint32_t b1) {
    asm volatile(
        "mma.sync.aligned.m16n8k16.row.col.f32.bf16.bf16.f32 "
        "{%0,%1,%2,%3}, {%4,%5,%6,%7}, {%8,%9}, {%0,%1,%2,%3};"
        : "+f"(d[0]), "+f"(d[1]), "+f"(d[2]), "+f"(d[3])
        : "r"(a[0]), "r"(a[1]), "r"(a[2]), "r"(a[3]), "r"(b0), "r"(b1));
}
__device__ __forceinline__ uint32_t smem_u32(const void* p) {
    uint32_t a;
    asm("{ .reg .u64 t; cvta.to.shared.u64 t, %1; cvt.u32.u64 %0, t; }"
        : "=r"(a) : "l"(p));
    return a;
}
__device__ __forceinline__ void cp16(uint32_t dst, const void* src) {
    asm volatile("cp.async.ca.shared.global [%0], [%1], 16;"
                 :: "r"(dst), "l"(src) : "memory");
}
#define CP_COMMIT() asm volatile("cp.async.commit_group;" ::: "memory")
#define CP_WAIT0()  asm volatile("cp.async.wait_group 0;" ::: "memory")

// =============== W -> Wt[224][256] bf16 hi/lo (transpose+split) ============
__global__ __launch_bounds__(256)
void conv_wt(const float* __restrict__ W, __nv_bfloat16* __restrict__ hi,
             __nv_bfloat16* __restrict__ lo) {
    int idx = blockIdx.x * 256 + threadIdx.x;     // over 224*256
    int n = idx >> 8, k = idx & 255;
    float v = (n < 200 && k < 200) ? W[k * 200 + n] : 0.f;
    __nv_bfloat16 h = __float2bfloat16(v);
    float r = v - __bfloat162float(h);
    hi[idx] = h;
    lo[idx] = __float2bfloat16(r);
}

// ============ mma.sync bf16-split GEMM: 64x224 block, 2 blocks/SM ==========
// smem (pitch 144B rows): AH 0 (64 rows), AL 9216, BH 18432 (224), BL 50688.
#define AH_OFF 0
#define AL_OFF 9216
#define BH_OFF 18432
#define BL_OFF 50688
#define GEMM_SMEM 82944

// A chunk: 64 rows x 64 cols fp32; thread -> row tid>>2, quarter tid&3.
__device__ __forceinline__ void load_a_chunk(const float* __restrict__ A,
                                             long row0, int tid, int kb,
                                             float4* abuf) {
    int r = tid >> 2, u4 = tid & 3;
    const float* ap = A + (row0 + r) * 200;
    #pragma unroll
    for (int q = 0; q < 4; q++) {
        int col0 = kb + u4 * 16 + q * 4;
        abuf[q] = (col0 < 200) ? *(const float4*)(ap + col0)
                               : make_float4(0.f, 0.f, 0.f, 0.f);
    }
}

__device__ __forceinline__ void conv_a_to_smem(char* smem, int tid,
                                               const float4* abuf) {
    int r = tid >> 2, u4 = tid & 3;
    char* ahp = smem + AH_OFF + r * 144 + u4 * 32;
    char* alp = smem + AL_OFF + r * 144 + u4 * 32;
    #pragma unroll
    for (int q = 0; q < 4; q++) {
        float4 v = abuf[q];
        uint32_t h01 = pkbf(v.x, v.y);
        uint32_t h23 = pkbf(v.z, v.w);
        float rx = v.x - bf_lo(h01), ry = v.y - bf_hi(h01);
        float rz = v.z - bf_lo(h23), rw = v.w - bf_hi(h23);
        uint32_t l01 = pkbf(rx, ry);
        uint32_t l23 = pkbf(rz, rw);
        *(uint32_t*)(ahp + q * 8)     = h01;
        *(uint32_t*)(ahp + q * 8 + 4) = h23;
        *(uint32_t*)(alp + q * 8)     = l01;
        *(uint32_t*)(alp + q * 8 + 4) = l23;
    }
}

// B chunk: 224 rows x 64 cols bf16 = 224 x 128B = 1792 x 16B per buffer;
// hi+lo = 3584 cp.async = 256 threads x 14 iterations exactly.
__device__ __forceinline__ void issue_b_cpasync(uint32_t sbase, int tid,
                                                const __nv_bfloat16* Bh,
                                                const __nv_bfloat16* Bl, int kb) {
    #pragma unroll
    for (int i = 0; i < 14; i++) {
        int e = tid + i * 256;            // 0..3583
        int buf = e >= 1792;
        int e2 = buf ? e - 1792 : e;
        int n = e2 >> 3, u = e2 & 7;      // 8 x 16B = 128B per row
        const __nv_bfloat16* src = (buf ? Bl : Bh) + n * 256 + kb + u * 8;
        uint32_t dst = sbase + (buf ? BL_OFF : BH_OFF) + n * 144 + u * 16;
        cp16(dst, src);
    }
    CP_COMMIT();
}

__global__ __launch_bounds__(256, 2)
void gemm_mma(const float* __restrict__ A,
              const __nv_bfloat16* __restrict__ Bh,
              const __nv_bfloat16* __restrict__ Bl,
              float* __restrict__ C) {
    extern __shared__ char smem[];
    const uint32_t sbase = smem_u32(smem);
    const int tid  = threadIdx.x;
    const int wid  = tid >> 5, lane = tid & 31;
    const int wm   = wid >> 2, wn = wid & 3;     // 2(M) x 4(N)
    const int g    = lane >> 2, t = lane & 3;
    const long row0 = (long)blockIdx.x * 64;

    float acc[2][7][4];
    #pragma unroll
    for (int mt = 0; mt < 2; mt++)
        #pragma unroll
        for (int nt = 0; nt < 7; nt++)
            #pragma unroll
            for (int e = 0; e < 4; e++) acc[mt][nt][e] = 0.f;

    float4 abuf[4];

    // prologue: chunk 0
    load_a_chunk(A, row0, tid, 0, abuf);
    issue_b_cpasync(sbase, tid, Bh, Bl, 0);
    conv_a_to_smem(smem, tid, abuf);
    CP_WAIT0();
    __syncthreads();

    #pragma unroll 1
    for (int c = 0; c < 4; c++) {
        // prefetch next A chunk into regs while MMAing this chunk
        if (c < 3) load_a_chunk(A, row0, tid, (c + 1) * 64, abuf);

        const uint32_t* AH32 = (const uint32_t*)(smem + AH_OFF);
        const uint32_t* AL32 = (const uint32_t*)(smem + AL_OFF);
        const uint32_t* BH32 = (const uint32_t*)(smem + BH_OFF);
        const uint32_t* BL32 = (const uint32_t*)(smem + BL_OFF);

        const int nst = (c < 3) ? 4 : 1;     // K = 208 total
        #pragma unroll 1
        for (int ks = 0; ks < nst; ks++) {
            uint32_t ah[2][4], al[2][4];
            #pragma unroll
            for (int mt = 0; mt < 2; mt++) {
                int r0 = wm * 32 + mt * 16 + g;
                int base = r0 * 36 + ks * 8 + t;
                ah[mt][0] = AH32[base];
                ah[mt][1] = AH32[base + 8 * 36];
                ah[mt][2] = AH32[base + 4];
                ah[mt][3] = AH32[base + 8 * 36 + 4];
                al[mt][0] = AL32[base];
                al[mt][1] = AL32[base + 8 * 36];
                al[mt][2] = AL32[base + 4];
                al[mt][3] = AL32[base + 8 * 36 + 4];
            }
            #pragma unroll
            for (int nt = 0; nt < 7; nt++) {
                int n = wn * 56 + nt * 8 + g;
                int bb = n * 36 + ks * 8 + t;
                uint32_t bh0 = BH32[bb], bh1 = BH32[bb + 4];
                uint32_t bl0 = BL32[bb], bl1 = BL32[bb + 4];
                #pragma unroll
                for (int mt = 0; mt < 2; mt++) {
                    mma_bf16(acc[mt][nt], ah[mt], bh0, bh1);
                    mma_bf16(acc[mt][nt], ah[mt], bl0, bl1);
                    mma_bf16(acc[mt][nt], al[mt], bh0, bh1);
                }
            }
        }

        if (c < 3) {
            __syncthreads();                      // MMA done -> smem reusable
            issue_b_cpasync(sbase, tid, Bh, Bl, (c + 1) * 64);
            conv_a_to_smem(smem, tid, abuf);
            CP_WAIT0();
            __syncthreads();
        }
    }

    // ---- epilogue ----
    #pragma unroll
    for (int mt = 0; mt < 2; mt++) {
        long r0 = row0 + wm * 32 + mt * 16 + g;
        #pragma unroll
        for (int nt = 0; nt < 7; nt++) {
            int col = wn * 56 + nt * 8 + t * 2;
            if (col < 200) {
                *(float2*)(C + r0 * 200 + col) =
                    make_float2(acc[mt][nt][0], acc[mt][nt][1]);
                *(float2*)(C + (r0 + 8) * 200 + col) =
                    make_float2(acc[mt][nt][2], acc[mt][nt][3]);
            }
        }
    }
}

// ================= Attention per (i, h): 256-thread split-K (R10) ===========
__global__ __launch_bounds__(256, 2)
void attn256(const float* __restrict__ Q, const float* __restrict__ K,
             const float* __restrict__ V, float* __restrict__ AW,
             float* __restrict__ CTX) {
    extern __shared__ float sm[];
    float* ks   = sm;                        // 128*20 (scale folded in)
    float* vs   = sm + 2560;                 // 128*20
    float* es   = sm + 5120;                 // 128*132
    float* sinv = sm + 5120 + 128 * 132;     // 128
    float* sp   = sinv + 128;                // 128 partial sums (half=1)
    float* op   = sp + 128;                  // 128*20 partial AV (half=1)

    const int i    = blockIdx.x;
    const int h    = blockIdx.y;
    const int tid  = threadIdx.x;
    const int q    = tid & 127;
    const int half = tid >> 7;
    const long rb  = (long)i * 128;
    const int hoff = h * 20;
    const float scale = 0.22360679774997896f;   // 1/sqrt(20)

    {
        float4* ks4 = (float4*)ks;
        float4* vs4 = (float4*)vs;
        #pragma unroll
        for (int e0 = 0; e0 < 3; e0++) {
            int e = tid + e0 * 256;
            if (e < 640) {
                int r = e / 5, c = e - r * 5;
                float4 k4 = *(const float4*)(K + (rb + r) * 200 + hoff + c * 4);
                k4.x *= scale; k4.y *= scale; k4.z *= scale; k4.w *= scale;
                ks4[e] = k4;
                vs4[e] = *(const float4*)(V + (rb + r) * 200 + hoff + c * 4);
            }
        }
    }
    float qr[20];
    {
        const float* qp = Q + (rb + q) * 200 + hoff;
        #pragma unroll
        for (int c = 0; c < 5; c++) {
            float4 t4 = *(const float4*)(qp + c * 4);
            qr[c * 4 + 0] = t4.x; qr[c * 4 + 1] = t4.y;
            qr[c * 4 + 2] = t4.z; qr[c * 4 + 3] = t4.w;
        }
    }
    __syncthreads();

    const int t0 = half * 64;
    float o[20];
    #pragma unroll
    for (int j = 0; j < 20; j++) o[j] = 0.f;
    float ssum0 = 0.f, ssum1 = 0.f;
    float eb0, eb1, eb2;
    float* myrow = es + q * 132;

    #pragma unroll 2
    for (int tt = 0; tt < 64; tt++) {
        const int t = t0 + tt;
        const float4* kt = (const float4*)(ks + t * 20);   // warp broadcast
        float4 k0 = kt[0], k1 = kt[1], k2 = kt[2], k3 = kt[3], k4 = kt[4];
        float a0 = qr[0] * k0.x + qr[4] * k1.x;
        float a1 = qr[1] * k0.y + qr[5] * k1.y;
        float a2 = qr[2] * k0.z + qr[6] * k1.z;
        float a3 = qr[3] * k0.w + qr[7] * k1.w;
        a0 += qr[8]  * k2.x + qr[12] * k3.x;
        a1 += qr[9]  * k2.y + qr[13] * k3.y;
        a2 += qr[10] * k2.z + qr[14] * k3.z;
        a3 += qr[11] * k2.w + qr[15] * k3.w;
        a0 += qr[16] * k4.x;
        a1 += qr[17] * k4.y;
        a2 += qr[18] * k4.z;
        a3 += qr[19] * k4.w;
        float e = __expf((a0 + a1) + (a2 + a3));
        if (tt & 1) ssum1 += e; else ssum0 += e;
        int ph = tt & 3;
        if (ph == 0)      eb0 = e;
        else if (ph == 1) eb1 = e;
        else if (ph == 2) eb2 = e;
        else *(float4*)(myrow + (t - 3)) = make_float4(eb0, eb1, eb2, e);
        const float4* vt = (const float4*)(vs + t * 20);   // warp broadcast
        #pragma unroll
        for (int c = 0; c < 5; c++) {
            float4 v4 = vt[c];
            o[c * 4 + 0] += e * v4.x; o[c * 4 + 1] += e * v4.y;
            o[c * 4 + 2] += e * v4.z; o[c * 4 + 3] += e * v4.w;
        }
    }
    float ssum = ssum0 + ssum1;

    if (half == 1) {
        sp[q] = ssum;
        float* od = op + q * 20;
        #pragma unroll
        for (int c = 0; c < 5; c++)
            *(float4*)(od + c * 4) = make_float4(o[c * 4 + 0], o[c * 4 + 1],
                                                 o[c * 4 + 2], o[c * 4 + 3]);
    }
    __syncthreads();
    if (half == 0) {
        const float inv = 1.0f / (ssum + sp[q]);
        sinv[q] = inv;
        const float* od = op + q * 20;
        float* cp = CTX + (rb + q) * 200 + hoff;
        #pragma unroll
        for (int c = 0; c < 5; c++) {
            float4 p4 = *(const float4*)(od + c * 4);
            *(float4*)(cp + c * 4) = make_float4(
                (o[c * 4 + 0] + p4.x) * inv, (o[c * 4 + 1] + p4.y) * inv,
                (o[c * 4 + 2] + p4.z) * inv, (o[c * 4 + 3] + p4.w) * inv);
        }
    }
    __syncthreads();

    {
        float4* awp = (float4*)(AW + (long)(i * 10 + h) * 16384);
        #pragma unroll
        for (int e0 = 0; e0 < 16; e0++) {
            int e = tid + e0 * 256;
            int s = e >> 5;
            int l = e & 31;
            float4 v4 = *(const float4*)(es + s * 132 + l * 4);
            float iv = sinv[s];
            awp[e] = make_float4(v4.x * iv, v4.y * iv, v4.z * iv, v4.w * iv);
        }
    }
}

// ---------------------------------------------------------------------------
extern "C" void kernel_launch(void* const* d_in, const int* in_sizes, int n_in,
                              void* d_out, int out_size) {
    const float* x  = (const float*)d_in[0];
    const float* wq = (const float*)d_in[1];
    const float* wk = (const float*)d_in[2];
    const float* wv = (const float*)d_in[3];

    float* attn = (float*)d_out;                       // 1024*10*128*128
    float* out  = (float*)d_out + 167772160L;          // 131072*200

    float *gq, *gk, *gv, *gctx;
    __nv_bfloat16 *whi, *wlo;
    cudaGetSymbolAddress((void**)&gq,   g_q);
    cudaGetSymbolAddress((void**)&gk,   g_k);
    cudaGetSymbolAddress((void**)&gv,   g_v);
    cudaGetSymbolAddress((void**)&gctx, g_ctx);
    cudaGetSymbolAddress((void**)&whi,  g_whi);
    cudaGetSymbolAddress((void**)&wlo,  g_wlo);

    const int AT_SMEM = 24832 * 4;   // 99328 B
    cudaFuncSetAttribute(gemm_mma, cudaFuncAttributeMaxDynamicSharedMemorySize, GEMM_SMEM);
    cudaFuncSetAttribute(attn256,  cudaFuncAttributeMaxDynamicSharedMemorySize, AT_SMEM);

    const int WSZ = 224 * 256;

    conv_wt<<<224, 256>>>(wq, whi + 0 * WSZ, wlo + 0 * WSZ);
    conv_wt<<<224, 256>>>(wk, whi + 1 * WSZ, wlo + 1 * WSZ);
    conv_wt<<<224, 256>>>(wv, whi + 2 * WSZ, wlo + 2 * WSZ);

    gemm_mma<<<2048, 256, GEMM_SMEM>>>(x, whi + 0 * WSZ, wlo + 0 * WSZ, gq);
    gemm_mma<<<2048, 256, GEMM_SMEM>>>(x, whi + 1 * WSZ, wlo + 1 * WSZ, gk);
    gemm_mma<<<2048, 256, GEMM_SMEM>>>(x, whi + 2 * WSZ, wlo + 2 * WSZ, gv);

    attn256<<<dim3(1024, 10), 256, AT_SMEM>>>(gq, gk, gv, attn, gctx);

    gemm_mma<<<2048, 256, GEMM_SMEM>>>(gctx, whi + 0 * WSZ, wlo + 0 * WSZ, out);
}

// round 13
// speedup vs baseline: 1.1351x; 1.0001x over previous
#include <cuda_runtime.h>
#include <cuda_bf16.h>
#include <cstdint>

// ---------------------------------------------------------------------------
// MultiHeadSelfAttention: B=128,H=128,F=8,D=200, nh=10, hd=20
// x flat: (131072, 200). Q/K/V/out projections: mma.sync bf16 3-pass split,
// 64x224 blocks, 2 blocks/SM, ldmatrix fragments. attn: 256-thr split-K fp32.
// ---------------------------------------------------------------------------

typedef unsigned long long u64;

// ---------------- fp32 scratch ----------------
__device__ float g_q[131072L * 200];
__device__ float g_k[131072L * 200];
__device__ float g_v[131072L * 200];
__device__ float g_ctx[131072L * 200];
// ---------------- bf16 split weights (transposed, padded to 224x256) -------
__device__ __nv_bfloat16 g_whi[3][224 * 256];
__device__ __nv_bfloat16 g_wlo[3][224 * 256];

// =========================== helpers =======================================
__device__ __forceinline__ uint32_t pkbf(float lo, float hi) {
    uint32_t r;
    asm("cvt.rn.bf16x2.f32 %0, %1, %2;" : "=r"(r) : "f"(hi), "f"(lo));
    return r;
}
__device__ __forceinline__ float bf_lo(uint32_t p) { return __uint_as_float(p << 16); }
__device__ __forceinline__ float bf_hi(uint32_t p) { return __uint_as_float(p & 0xFFFF0000u); }

__device__ __forceinline__ void mma_bf16(float* d, const uint32_t* a,
                                         uint32_t b0, uint32_t b1) {
    asm volatile(
        "mma.sync.aligned.m16n8k16.row.col.f32.bf16.bf16.f32 "
        "{%0,%1,%2,%3}, {%4,%5,%6,%7}, {%8,%9}, {%0,%1,%2,%3};"
        : "+f"(d[0]), "+f"(d[1]), "+f"(d[2]), "+f"(d[3])
        : "r"(a[0]), "r"(a[1]), "r"(a[2]), "r"(a[3]), "r"(b0), "r"(b1));
}
__device__ __forceinline__ void ldsm_x4(uint32_t* r, uint32_t addr) {
    asm volatile("ldmatrix.sync.aligned.m8n8.x4.shared.b16 {%0,%1,%2,%3}, [%4];"
        : "=r"(r[0]), "=r"(r[1]), "=r"(r[2]), "=r"(r[3]) : "r"(addr));
}
__device__ __forceinline__ void ldsm_x2(uint32_t* r, uint32_t addr) {
    asm volatile("ldmatrix.sync.aligned.m8n8.x2.shared.b16 {%0,%1}, [%2];"
        : "=r"(r[0]), "=r"(r[1]) : "r"(addr));
}
__device__ __forceinline__ uint32_t smem_u32(const void* p) {
    uint32_t a;
    asm("{ .reg .u64 t; cvta.to.shared.u64 t, %1; cvt.u32.u64 %0, t; }"
        : "=r"(a) : "l"(p));
    return a;
}
__device__ __forceinline__ void cp16(uint32_t dst, const void* src) {
    asm volatile("cp.async.ca.shared.global [%0], [%1], 16;"
                 :: "r"(dst), "l"(src) : "memory");
}
#define CP_COMMIT() asm volatile("cp.async.commit_group;" ::: "memory")
#define CP_WAIT0()  asm volatile("cp.async.wait_group 0;" ::: "memory")

// ====== W{q,k,v} -> Wt[224][256] bf16 hi/lo (transpose+split), one launch ===
__global__ __launch_bounds__(256)
void conv_wt3(const float* __restrict__ wq, const float* __restrict__ wk,
              const float* __restrict__ wv, __nv_bfloat16* __restrict__ hi,
              __nv_bfloat16* __restrict__ lo) {
    const int w = blockIdx.y;
    const float* W = (w == 0) ? wq : (w == 1) ? wk : wv;
    int idx = blockIdx.x * 256 + threadIdx.x;     // over 224*256
    int n = idx >> 8, k = idx & 255;
    float v = (n < 200 && k < 200) ? W[k * 200 + n] : 0.f;
    __nv_bfloat16 h = __float2bfloat16(v);
    float r = v - __bfloat162float(h);
    hi[(long)w * (224 * 256) + idx] = h;
    lo[(long)w * (224 * 256) + idx] = __float2bfloat16(r);
}

// ============ mma.sync bf16-split GEMM: 64x224 block, 2 blocks/SM ==========
// smem (pitch 144B rows): AH 0 (64 rows), AL 9216, BH 18432 (224), BL 50688.
#define AH_OFF 0
#define AL_OFF 9216
#define BH_OFF 18432
#define BL_OFF 50688
#define GEMM_SMEM 82944

// A chunk: 64 rows x 64 cols fp32; thread -> row tid>>2, quarter tid&3.
__device__ __forceinline__ void load_a_chunk(const float* __restrict__ A,
                                             long row0, int tid, int kb,
                                             float4* abuf) {
    int r = tid >> 2, u4 = tid & 3;
    const float* ap = A + (row0 + r) * 200;
    #pragma unroll
    for (int q = 0; q < 4; q++) {
        int col0 = kb + u4 * 16 + q * 4;
        abuf[q] = (col0 < 200) ? *(const float4*)(ap + col0)
                               : make_float4(0.f, 0.f, 0.f, 0.f);
    }
}

__device__ __forceinline__ void conv_a_to_smem(char* smem, int tid,
                                               const float4* abuf) {
    int r = tid >> 2, u4 = tid & 3;
    char* ahp = smem + AH_OFF + r * 144 + u4 * 32;
    char* alp = smem + AL_OFF + r * 144 + u4 * 32;
    #pragma unroll
    for (int q = 0; q < 4; q++) {
        float4 v = abuf[q];
        uint32_t h01 = pkbf(v.x, v.y);
        uint32_t h23 = pkbf(v.z, v.w);
        float rx = v.x - bf_lo(h01), ry = v.y - bf_hi(h01);
        float rz = v.z - bf_lo(h23), rw = v.w - bf_hi(h23);
        uint32_t l01 = pkbf(rx, ry);
        uint32_t l23 = pkbf(rz, rw);
        *(uint32_t*)(ahp + q * 8)     = h01;
        *(uint32_t*)(ahp + q * 8 + 4) = h23;
        *(uint32_t*)(alp + q * 8)     = l01;
        *(uint32_t*)(alp + q * 8 + 4) = l23;
    }
}

// B chunk: 224 rows x 64 cols bf16 = 1792 x 16B per buffer; hi+lo = 3584
// cp.async = 256 threads x 14.
__device__ __forceinline__ void issue_b_cpasync(uint32_t sbase, int tid,
                                                const __nv_bfloat16* Bh,
                                                const __nv_bfloat16* Bl, int kb) {
    #pragma unroll
    for (int i = 0; i < 14; i++) {
        int e = tid + i * 256;            // 0..3583
        int buf = e >= 1792;
        int e2 = buf ? e - 1792 : e;
        int n = e2 >> 3, u = e2 & 7;      // 8 x 16B = 128B per row
        const __nv_bfloat16* src = (buf ? Bl : Bh) + n * 256 + kb + u * 8;
        uint32_t dst = sbase + (buf ? BL_OFF : BH_OFF) + n * 144 + u * 16;
        cp16(dst, src);
    }
    CP_COMMIT();
}

// 6 MMAs (3-pass split) for one nt given fragment regs.
__device__ __forceinline__ void mma_nt(float* acc0, float* acc1,
                                       const uint32_t* ah0, const uint32_t* ah1,
                                       const uint32_t* al0, const uint32_t* al1,
                                       uint32_t bh0, uint32_t bh1,
                                       uint32_t bl0, uint32_t bl1) {
    mma_bf16(acc0, ah0, bh0, bh1);
    mma_bf16(acc0, ah0, bl0, bl1);
    mma_bf16(acc0, al0, bh0, bh1);
    mma_bf16(acc1, ah1, bh0, bh1);
    mma_bf16(acc1, ah1, bl0, bl1);
    mma_bf16(acc1, al1, bh0, bh1);
}

__global__ __launch_bounds__(256, 2)
void gemm_mma(const float* __restrict__ A,
              const __nv_bfloat16* __restrict__ Bh,
              const __nv_bfloat16* __restrict__ Bl,
              float* __restrict__ C) {
    extern __shared__ char smem[];
    const uint32_t sbase = smem_u32(smem);
    const int tid  = threadIdx.x;
    const int wid  = tid >> 5, lane = tid & 31;
    const int wm   = wid >> 2, wn = wid & 3;     // 2(M) x 4(N)
    const int g    = lane >> 2, t = lane & 3;
    const long row0 = (long)blockIdx.x * 64;

    // ldmatrix per-lane base addresses (constant across chunks; +32B per ks)
    // A x4 tile: rows (wm*32 + mt*16 + lane&15), col-half (lane>>4)*16B
    const uint32_t aA = sbase + AH_OFF
        + (uint32_t)(wm * 32 + (lane & 15)) * 144 + (uint32_t)(lane >> 4) * 16;
    // B x4 pair tiles: row = wn*56 + p*16 + (lane&7) + ((lane>>4)&1)*8,
    //                  col-half = ((lane>>3)&1)*16B
    const uint32_t aB = sbase + BH_OFF
        + (uint32_t)(wn * 56 + (lane & 7) + ((lane >> 4) & 1) * 8) * 144
        + (uint32_t)((lane >> 3) & 1) * 16;

    float acc[2][7][4];
    #pragma unroll
    for (int mt = 0; mt < 2; mt++)
        #pragma unroll
        for (int nt = 0; nt < 7; nt++)
            #pragma unroll
            for (int e = 0; e < 4; e++) acc[mt][nt][e] = 0.f;

    float4 abuf[4];

    // prologue: chunk 0
    load_a_chunk(A, row0, tid, 0, abuf);
    issue_b_cpasync(sbase, tid, Bh, Bl, 0);
    conv_a_to_smem(smem, tid, abuf);
    CP_WAIT0();
    __syncthreads();

    #pragma unroll 1
    for (int c = 0; c < 4; c++) {
        if (c < 3) load_a_chunk(A, row0, tid, (c + 1) * 64, abuf);

        const int nst = (c < 3) ? 4 : 1;     // K = 208 total
        #pragma unroll 1
        for (int ks = 0; ks < nst; ks++) {
            const uint32_t ao = (uint32_t)ks * 32;
            uint32_t ah0[4], ah1[4], al0[4], al1[4];
            ldsm_x4(ah0, aA + ao);                       // mt0 hi
            ldsm_x4(ah1, aA + 2304 + ao);                // mt1 hi (+16 rows)
            ldsm_x4(al0, aA + 9216 + ao);                // mt0 lo
            ldsm_x4(al1, aA + 11520 + ao);               // mt1 lo
            #pragma unroll
            for (int p = 0; p < 3; p++) {                // nt = 2p, 2p+1
                uint32_t bh[4], bl[4];
                ldsm_x4(bh, aB + p * 2304 + ao);
                ldsm_x4(bl, aB + p * 2304 + 32256 + ao);
                mma_nt(acc[0][2 * p],     acc[1][2 * p],
                       ah0, ah1, al0, al1, bh[0], bh[1], bl[0], bl[1]);
                mma_nt(acc[0][2 * p + 1], acc[1][2 * p + 1],
                       ah0, ah1, al0, al1, bh[2], bh[3], bl[2], bl[3]);
            }
            {                                            // nt = 6
                uint32_t bh[2], bl[2];
                ldsm_x2(bh, aB + 6912 + ao);
                ldsm_x2(bl, aB + 6912 + 32256 + ao);
                mma_nt(acc[0][6], acc[1][6],
                       ah0, ah1, al0, al1, bh[0], bh[1], bl[0], bl[1]);
            }
        }

        if (c < 3) {
            __syncthreads();                      // MMA done -> smem reusable
            issue_b_cpasync(sbase, tid, Bh, Bl, (c + 1) * 64);
            conv_a_to_smem(smem, tid, abuf);
            CP_WAIT0();
            __syncthreads();
        }
    }

    // ---- epilogue ----
    #pragma unroll
    for (int mt = 0; mt < 2; mt++) {
        long r0 = row0 + wm * 32 + mt * 16 + g;
        #pragma unroll
        for (int nt = 0; nt < 7; nt++) {
            int col = wn * 56 + nt * 8 + t * 2;
            if (col < 200) {
                *(float2*)(C + r0 * 200 + col) =
                    make_float2(acc[mt][nt][0], acc[mt][nt][1]);
                *(float2*)(C + (r0 + 8) * 200 + col) =
                    make_float2(acc[mt][nt][2], acc[mt][nt][3]);
            }
        }
    }
}

// ================= Attention per (i, h): 256-thread split-K (R10) ===========
__global__ __launch_bounds__(256, 2)
void attn256(const float* __restrict__ Q, const float* __restrict__ K,
             const float* __restrict__ V, float* __restrict__ AW,
             float* __restrict__ CTX) {
    extern __shared__ float sm[];
    float* ks   = sm;                        // 128*20 (scale folded in)
    float* vs   = sm + 2560;                 // 128*20
    float* es   = sm + 5120;                 // 128*132
    float* sinv = sm + 5120 + 128 * 132;     // 128
    float* sp   = sinv + 128;                // 128 partial sums (half=1)
    float* op   = sp + 128;                  // 128*20 partial AV (half=1)

    const int i    = blockIdx.x;
    const int h    = blockIdx.y;
    const int tid  = threadIdx.x;
    const int q    = tid & 127;
    const int half = tid >> 7;
    const long rb  = (long)i * 128;
    const int hoff = h * 20;
    const float scale = 0.22360679774997896f;   // 1/sqrt(20)

    {
        float4* ks4 = (float4*)ks;
        float4* vs4 = (float4*)vs;
        #pragma unroll
        for (int e0 = 0; e0 < 3; e0++) {
            int e = tid + e0 * 256;
            if (e < 640) {
                int r = e / 5, c = e - r * 5;
                float4 k4 = *(const float4*)(K + (rb + r) * 200 + hoff + c * 4);
                k4.x *= scale; k4.y *= scale; k4.z *= scale; k4.w *= scale;
                ks4[e] = k4;
                vs4[e] = *(const float4*)(V + (rb + r) * 200 + hoff + c * 4);
            }
        }
    }
    float qr[20];
    {
        const float* qp = Q + (rb + q) * 200 + hoff;
        #pragma unroll
        for (int c = 0; c < 5; c++) {
            float4 t4 = *(const float4*)(qp + c * 4);
            qr[c * 4 + 0] = t4.x; qr[c * 4 + 1] = t4.y;
            qr[c * 4 + 2] = t4.z; qr[c * 4 + 3] = t4.w;
        }
    }
    __syncthreads();

    const int t0 = half * 64;
    float o[20];
    #pragma unroll
    for (int j = 0; j < 20; j++) o[j] = 0.f;
    float ssum0 = 0.f, ssum1 = 0.f;
    float eb0, eb1, eb2;
    float* myrow = es + q * 132;

    #pragma unroll 2
    for (int tt = 0; tt < 64; tt++) {
        const int t = t0 + tt;
        const float4* kt = (const float4*)(ks + t * 20);   // warp broadcast
        float4 k0 = kt[0], k1 = kt[1], k2 = kt[2], k3 = kt[3], k4 = kt[4];
        float a0 = qr[0] * k0.x + qr[4] * k1.x;
        float a1 = qr[1] * k0.y + qr[5] * k1.y;
        float a2 = qr[2] * k0.z + qr[6] * k1.z;
        float a3 = qr[3] * k0.w + qr[7] * k1.w;
        a0 += qr[8]  * k2.x + qr[12] * k3.x;
        a1 += qr[9]  * k2.y + qr[13] * k3.y;
        a2 += qr[10] * k2.z + qr[14] * k3.z;
        a3 += qr[11] * k2.w + qr[15] * k3.w;
        a0 += qr[16] * k4.x;
        a1 += qr[17] * k4.y;
        a2 += qr[18] * k4.z;
        a3 += qr[19] * k4.w;
        float e = __expf((a0 + a1) + (a2 + a3));
        if (tt & 1) ssum1 += e; else ssum0 += e;
        int ph = tt & 3;
        if (ph == 0)      eb0 = e;
        else if (ph == 1) eb1 = e;
        else if (ph == 2) eb2 = e;
        else *(float4*)(myrow + (t - 3)) = make_float4(eb0, eb1, eb2, e);
        const float4* vt = (const float4*)(vs + t * 20);   // warp broadcast
        #pragma unroll
        for (int c = 0; c < 5; c++) {
            float4 v4 = vt[c];
            o[c * 4 + 0] += e * v4.x; o[c * 4 + 1] += e * v4.y;
            o[c * 4 + 2] += e * v4.z; o[c * 4 + 3] += e * v4.w;
        }
    }
    float ssum = ssum0 + ssum1;

    if (half == 1) {
        sp[q] = ssum;
        float* od = op + q * 20;
        #pragma unroll
        for (int c = 0; c < 5; c++)
            *(float4*)(od + c * 4) = make_float4(o[c * 4 + 0], o[c * 4 + 1],
                                                 o[c * 4 + 2], o[c * 4 + 3]);
    }
    __syncthreads();
    if (half == 0) {
        const float inv = 1.0f / (ssum + sp[q]);
        sinv[q] = inv;
        const float* od = op + q * 20;
        float* cp = CTX + (rb + q) * 200 + hoff;
        #pragma unroll
        for (int c = 0; c < 5; c++) {
            float4 p4 = *(const float4*)(od + c * 4);
            *(float4*)(cp + c * 4) = make_float4(
                (o[c * 4 + 0] + p4.x) * inv, (o[c * 4 + 1] + p4.y) * inv,
                (o[c * 4 + 2] + p4.z) * inv, (o[c * 4 + 3] + p4.w) * inv);
        }
    }
    __syncthreads();

    {
        float4* awp = (float4*)(AW + (long)(i * 10 + h) * 16384);
        #pragma unroll
        for (int e0 = 0; e0 < 16; e0++) {
            int e = tid + e0 * 256;
            int s = e >> 5;
            int l = e & 31;
            float4 v4 = *(const float4*)(es + s * 132 + l * 4);
            float iv = sinv[s];
            awp[e] = make_float4(v4.x * iv, v4.y * iv, v4.z * iv, v4.w * iv);
        }
    }
}

// ---------------------------------------------------------------------------
extern "C" void kernel_launch(void* const* d_in, const int* in_sizes, int n_in,
                              void* d_out, int out_size) {
    const float* x  = (const float*)d_in[0];
    const float* wq = (const float*)d_in[1];
    const float* wk = (const float*)d_in[2];
    const float* wv = (const float*)d_in[3];

    float* attn = (float*)d_out;                       // 1024*10*128*128
    float* out  = (float*)d_out + 167772160L;          // 131072*200

    float *gq, *gk, *gv, *gctx;
    __nv_bfloat16 *whi, *wlo;
    cudaGetSymbolAddress((void**)&gq,   g_q);
    cudaGetSymbolAddress((void**)&gk,   g_k);
    cudaGetSymbolAddress((void**)&gv,   g_v);
    cudaGetSymbolAddress((void**)&gctx, g_ctx);
    cudaGetSymbolAddress((void**)&whi,  g_whi);
    cudaGetSymbolAddress((void**)&wlo,  g_wlo);

    const int AT_SMEM = 24832 * 4;   // 99328 B
    cudaFuncSetAttribute(gemm_mma, cudaFuncAttributeMaxDynamicSharedMemorySize, GEMM_SMEM);
    cudaFuncSetAttribute(attn256,  cudaFuncAttributeMaxDynamicSharedMemorySize, AT_SMEM);

    const int WSZ = 224 * 256;

    conv_wt3<<<dim3(224, 3), 256>>>(wq, wk, wv, whi, wlo);

    gemm_mma<<<2048, 256, GEMM_SMEM>>>(x, whi + 0 * WSZ, wlo + 0 * WSZ, gq);
    gemm_mma<<<2048, 256, GEMM_SMEM>>>(x, whi + 1 * WSZ, wlo + 1 * WSZ, gk);
    gemm_mma<<<2048, 256, GEMM_SMEM>>>(x, whi + 2 * WSZ, wlo + 2 * WSZ, gv);

    attn256<<<dim3(1024, 10), 256, AT_SMEM>>>(gq, gk, gv, attn, gctx);

    gemm_mma<<<2048, 256, GEMM_SMEM>>>(gctx, whi + 0 * WSZ, wlo + 0 * WSZ, out);
}